// round 5
// baseline (speedup 1.0000x reference)
#include <cuda_runtime.h>
#include <math.h>

#define BB 64
#define TT 512
#define EE 256
#define HH 256
#define KK 9
#define G4 1024              // 4*H
#define MTOT (BB*TT)         // 32768

// ---------------- scratch (device globals; no allocations allowed) ----------
__device__ float g_gx_f[(size_t)MTOT * G4];   // forward input-gate preacts (+bias)
__device__ float g_gx_b[(size_t)MTOT * G4];   // backward input-gate preacts (+bias)
__device__ float g_emis[(size_t)MTOT * KK];   // emissions
__device__ float g_loss[BB];                  // per-batch (num - denom)

__device__ __forceinline__ float sigf(float x) { return 1.0f / (1.0f + expf(-x)); }

// ---------------- zero feats region --------------------------------------
__global__ void zero_kernel(float* __restrict__ p, int n) {
    int i = blockIdx.x * blockDim.x + threadIdx.x;
    if (i < n) p[i] = 0.0f;
}

// ---------------- fused embedding-gather + input GEMM ---------------------
// C[m, n] = sum_k word_vec[word_inputs[m], k] * W_ih[n, k] + bias[n]
// Tile 128x128, BK=8, 256 threads, 8x8 micro-tile. grid.z selects direction.
__global__ __launch_bounds__(256, 2)
void gemm_kernel(const int* __restrict__ word_inputs,
                 const int* __restrict__ lens,
                 const float* __restrict__ word_vec,
                 const float* __restrict__ Wf, const float* __restrict__ bf,
                 const float* __restrict__ Wb, const float* __restrict__ bb)
{
    const int dir = blockIdx.z;
    const float* __restrict__ Wih  = dir ? Wb : Wf;
    const float* __restrict__ bias = dir ? bb : bf;
    float* __restrict__ gx = dir ? g_gx_b : g_gx_f;

    const int m0 = blockIdx.y * 128;
    const int n0 = blockIdx.x * 128;
    const int bidx = m0 >> 9;        // 512/128=4 blocks per batch, aligned
    const int t0   = m0 & 511;
    if (t0 >= lens[bidx]) return;    // gx rows t>=L never read downstream

    __shared__ float As[8][128];
    __shared__ float Bs[8][128];
    __shared__ int   sIdx[128];

    const int tid = threadIdx.x;
    if (tid < 128) sIdx[tid] = word_inputs[m0 + tid];
    __syncthreads();

    const int lr = tid >> 1;           // 0..127 row within tile
    const int kq = (tid & 1) * 4;      // 0 or 4
    const int ty = tid >> 4, tx = tid & 15;

    const float* __restrict__ arow = word_vec + (size_t)sIdx[lr] * EE;
    const float* __restrict__ brow = Wih + (size_t)(n0 + lr) * EE;

    float acc[8][8];
#pragma unroll
    for (int i = 0; i < 8; i++)
#pragma unroll
        for (int j = 0; j < 8; j++) acc[i][j] = 0.0f;

    for (int k0 = 0; k0 < EE; k0 += 8) {
        float4 av = *(const float4*)(arow + k0 + kq);
        float4 bv = *(const float4*)(brow + k0 + kq);
        __syncthreads();
        As[kq + 0][lr] = av.x; As[kq + 1][lr] = av.y;
        As[kq + 2][lr] = av.z; As[kq + 3][lr] = av.w;
        Bs[kq + 0][lr] = bv.x; Bs[kq + 1][lr] = bv.y;
        Bs[kq + 2][lr] = bv.z; Bs[kq + 3][lr] = bv.w;
        __syncthreads();
#pragma unroll
        for (int kk = 0; kk < 8; kk++) {
            float4 a0 = *(const float4*)&As[kk][ty * 8];
            float4 a1 = *(const float4*)&As[kk][ty * 8 + 4];
            float4 b0 = *(const float4*)&Bs[kk][tx * 8];
            float4 b1 = *(const float4*)&Bs[kk][tx * 8 + 4];
            float a[8] = {a0.x, a0.y, a0.z, a0.w, a1.x, a1.y, a1.z, a1.w};
            float b[8] = {b0.x, b0.y, b0.z, b0.w, b1.x, b1.y, b1.z, b1.w};
#pragma unroll
            for (int i = 0; i < 8; i++)
#pragma unroll
                for (int j = 0; j < 8; j++)
                    acc[i][j] = fmaf(a[i], b[j], acc[i][j]);
        }
    }

    const float* bsrc = bias + n0 + tx * 8;
    float4 bb0 = *(const float4*)(bsrc);
    float4 bb1 = *(const float4*)(bsrc + 4);
    float bvals[8] = {bb0.x, bb0.y, bb0.z, bb0.w, bb1.x, bb1.y, bb1.z, bb1.w};
#pragma unroll
    for (int i = 0; i < 8; i++) {
        int m = m0 + ty * 8 + i;
        float* dst = gx + (size_t)m * G4 + n0 + tx * 8;
        float4 o0 = make_float4(acc[i][0] + bvals[0], acc[i][1] + bvals[1],
                                acc[i][2] + bvals[2], acc[i][3] + bvals[3]);
        float4 o1 = make_float4(acc[i][4] + bvals[4], acc[i][5] + bvals[5],
                                acc[i][6] + bvals[6], acc[i][7] + bvals[7]);
        *(float4*)(dst) = o0;
        *(float4*)(dst + 4) = o1;
    }
}

// ---------------- bidirectional LSTM recurrence ---------------------------
// grid (32, 2): blockIdx.x = batch pair, blockIdx.y = direction. 512 threads.
// Thread tid owns gate rows tid and tid+512 for both batches of the pair.
// Rows: [0,256)=i, [256,512)=f, [512,768)=g, [768,1024)=o.
// Backward direction consumes gx_b at t = L-1-s and writes h at t = L-1-s.
__global__ __launch_bounds__(512, 1)
void lstm_kernel(const int* __restrict__ lens, float* __restrict__ feats,
                 const float* __restrict__ Whh_f, const float* __restrict__ Whh_b)
{
    const int dir = blockIdx.y;
    const int b0 = blockIdx.x * 2, b1 = b0 + 1;
    const float* __restrict__ Whh = dir ? Whh_b : Whh_f;
    const float* __restrict__ gx  = dir ? g_gx_b : g_gx_f;
    const int L0 = lens[b0], L1 = lens[b1];
    const int Lmax = (L0 > L1) ? L0 : L1;

    __shared__ float h0[HH], h1[HH], ig0[HH], ig1[HH];
    const int tid = threadIdx.x;
    if (tid < HH) { h0[tid] = 0.0f; h1[tid] = 0.0f; }
    float c0 = 0.0f, c1 = 0.0f;

    const float4* __restrict__ wA = (const float4*)(Whh + (size_t)tid * HH);
    const float4* __restrict__ wB = (const float4*)(Whh + (size_t)(tid + 512) * HH);
    __syncthreads();

    for (int s = 0; s < Lmax; s++) {
        float aA0 = 0, aA1 = 0, aB0 = 0, aB1 = 0;
        const float4* __restrict__ Hp0 = (const float4*)h0;
        const float4* __restrict__ Hp1 = (const float4*)h1;
#pragma unroll 8
        for (int k = 0; k < HH / 4; k++) {
            float4 ha = Hp0[k], hb = Hp1[k];
            float4 wa = wA[k],  wb = wB[k];
            aA0 = fmaf(wa.x, ha.x, aA0); aA0 = fmaf(wa.y, ha.y, aA0);
            aA0 = fmaf(wa.z, ha.z, aA0); aA0 = fmaf(wa.w, ha.w, aA0);
            aA1 = fmaf(wa.x, hb.x, aA1); aA1 = fmaf(wa.y, hb.y, aA1);
            aA1 = fmaf(wa.z, hb.z, aA1); aA1 = fmaf(wa.w, hb.w, aA1);
            aB0 = fmaf(wb.x, ha.x, aB0); aB0 = fmaf(wb.y, ha.y, aB0);
            aB0 = fmaf(wb.z, ha.z, aB0); aB0 = fmaf(wb.w, ha.w, aB0);
            aB1 = fmaf(wb.x, hb.x, aB1); aB1 = fmaf(wb.y, hb.y, aB1);
            aB1 = fmaf(wb.z, hb.z, aB1); aB1 = fmaf(wb.w, hb.w, aB1);
        }
        const bool act0 = s < L0, act1 = s < L1;
        const int t0 = dir ? (L0 - 1 - s) : s;
        const int t1 = dir ? (L1 - 1 - s) : s;
        const size_t base0 = (size_t)(b0 * TT + t0) * G4;
        const size_t base1 = (size_t)(b1 * TT + t1) * G4;

        float fv0 = 0, ov0 = 0, fv1 = 0, ov1 = 0;
        if (tid < HH) {
            if (act0) {
                float iv = aA0 + gx[base0 + tid];
                float gv = aB0 + gx[base0 + 512 + tid];
                ig0[tid] = sigf(iv) * tanhf(gv);
            }
            if (act1) {
                float iv = aA1 + gx[base1 + tid];
                float gv = aB1 + gx[base1 + 512 + tid];
                ig1[tid] = sigf(iv) * tanhf(gv);
            }
        } else {
            if (act0) { fv0 = aA0 + gx[base0 + tid]; ov0 = aB0 + gx[base0 + 512 + tid]; }
            if (act1) { fv1 = aA1 + gx[base1 + tid]; ov1 = aB1 + gx[base1 + 512 + tid]; }
        }
        __syncthreads();
        if (tid >= HH) {
            const int j = tid - HH;
            if (act0) {
                c0 = fmaf(sigf(fv0), c0, ig0[j]);
                float hv = sigf(ov0) * tanhf(c0);
                h0[j] = hv;
                feats[(size_t)(b0 * TT + t0) * (2 * HH) + dir * HH + j] = hv;
            }
            if (act1) {
                c1 = fmaf(sigf(fv1), c1, ig1[j]);
                float hv = sigf(ov1) * tanhf(c1);
                h1[j] = hv;
                feats[(size_t)(b1 * TT + t1) * (2 * HH) + dir * HH + j] = hv;
            }
        }
        __syncthreads();
    }
}

// ---------------- emissions: feats @ W_out^T + b_out ----------------------
__global__ void emis_kernel(const float* __restrict__ feats,
                            const float* __restrict__ Wout,
                            const float* __restrict__ bout)
{
    __shared__ float sW[KK][2 * HH];   // 18 KB
    const int tid = threadIdx.x;
    for (int i = tid; i < KK * 2 * HH; i += 256)
        sW[i / (2 * HH)][i % (2 * HH)] = Wout[i];
    __syncthreads();

    const int warp = tid >> 5, lane = tid & 31;
    const int row = blockIdx.x * 8 + warp;
    const float* __restrict__ fr = feats + (size_t)row * (2 * HH);
    float acc[KK];
#pragma unroll
    for (int k = 0; k < KK; k++) acc[k] = 0.0f;
#pragma unroll 4
    for (int it = 0; it < 16; it++) {
        float x = fr[it * 32 + lane];
#pragma unroll
        for (int k = 0; k < KK; k++) acc[k] = fmaf(x, sW[k][it * 32 + lane], acc[k]);
    }
#pragma unroll
    for (int k = 0; k < KK; k++) {
        float v = acc[k];
#pragma unroll
        for (int off = 16; off; off >>= 1) v += __shfl_xor_sync(0xffffffffu, v, off);
        if (lane == 0) g_emis[(size_t)row * KK + k] = v + bout[k];
    }
}

// ---------------- CRF: alpha + numerator (warp0), viterbi + preds (warp1) --
__global__ void crf_kernel(const int* __restrict__ lens, const int* __restrict__ labels,
                           const float* __restrict__ start_t, const float* __restrict__ end_t,
                           const float* __restrict__ trans, float* __restrict__ preds_out)
{
    const int b = blockIdx.x;
    const int L = lens[b];
    const int tid = threadIdx.x, warp = tid >> 5, lane = tid & 31;
    const float* __restrict__ em = g_emis + (size_t)b * TT * KK;
    __shared__ unsigned char hist[TT][KK];   // backpointers, rows [0, L-2]

    const float NEG = -1e30f;
    const int j = lane;
    float tr[KK];
#pragma unroll
    for (int i = 0; i < KK; i++) tr[i] = (j < KK) ? trans[i * KK + j] : 0.0f;

    if (warp == 0) {
        // ---- alpha (log-partition) ----
        float score = (j < KK) ? (start_t[j] + em[j]) : NEG;
        for (int t = 1; t < L; t++) {
            float v[KK], mx = NEG;
#pragma unroll
            for (int i = 0; i < KK; i++) {
                v[i] = __shfl_sync(0xffffffffu, score, i) + tr[i];
                mx = fmaxf(mx, v[i]);
            }
            float sum = 0.0f;
#pragma unroll
            for (int i = 0; i < KK; i++) sum += __expf(v[i] - mx);
            float e = (j < KK) ? em[t * KK + j] : 0.0f;
            float nxt = mx + __logf(sum) + e;
            if (j < KK) score = nxt;
        }
        float z = (j < KK) ? (score + end_t[j]) : NEG;
        float mz = z;
#pragma unroll
        for (int off = 16; off; off >>= 1) mz = fmaxf(mz, __shfl_xor_sync(0xffffffffu, mz, off));
        float se = (j < KK) ? __expf(z - mz) : 0.0f;
#pragma unroll
        for (int off = 16; off; off >>= 1) se += __shfl_xor_sync(0xffffffffu, se, off);
        float denom = mz + __logf(se);

        // ---- numerator (gold-path score) ----
        const int* __restrict__ lab = labels + b * TT;
        float acc = 0.0f;
        for (int t = 1 + lane; t < L; t += 32) {
            int yp = lab[t - 1], y = lab[t];
            acc += trans[yp * KK + y] + em[t * KK + y];
        }
#pragma unroll
        for (int off = 16; off; off >>= 1) acc += __shfl_xor_sync(0xffffffffu, acc, off);
        if (lane == 0) {
            int y0 = lab[0], yl = lab[L - 1];
            float num = acc + start_t[y0] + em[y0] + end_t[yl];
            g_loss[b] = num - denom;
        }
    } else {
        // ---- viterbi ----
        float score = (j < KK) ? (start_t[j] + em[j]) : NEG;
        for (int t = 1; t < L; t++) {
            float best = NEG; int barg = 0;
#pragma unroll
            for (int i = 0; i < KK; i++) {
                float v = __shfl_sync(0xffffffffu, score, i) + tr[i];
                if (v > best) { best = v; barg = i; }   // first-max on ties
            }
            if (j < KK) {
                hist[t - 1][j] = (unsigned char)barg;
                score = best + em[t * KK + j];
            }
        }
        float z = (j < KK) ? (score + end_t[j]) : NEG;
        int idx = j;
#pragma unroll
        for (int off = 16; off; off >>= 1) {
            float oz = __shfl_xor_sync(0xffffffffu, z, off);
            int   oi = __shfl_xor_sync(0xffffffffu, idx, off);
            if (oz > z || (oz == z && oi < idx)) { z = oz; idx = oi; }
        }
        int best_last = __shfl_sync(0xffffffffu, idx, 0);

        float* __restrict__ po = preds_out + (size_t)b * TT;
        for (int t = L + lane; t < TT; t += 32) po[t] = 0.0f;  // masked region
        if (lane == 0) {
            int cur = best_last;
            po[L - 1] = (float)cur;
            for (int t = L - 2; t >= 0; t--) { cur = hist[t][cur]; po[t] = (float)cur; }
        }
    }
}

// ---------------- deterministic loss reduction ----------------------------
__global__ void finalize_kernel(float* __restrict__ out) {
    if (threadIdx.x == 0) {
        float s = 0.0f;
        for (int i = 0; i < BB; i++) s += g_loss[i];   // fixed order -> deterministic
        out[0] = -s / (float)BB;
    }
}

// ---------------- launch ---------------------------------------------------
extern "C" void kernel_launch(void* const* d_in, const int* in_sizes, int n_in,
                              void* d_out, int out_size) {
    const int*   wi    = (const int*)d_in[0];    // word_inputs (B,T)
    const int*   lens  = (const int*)d_in[1];    // word_seq_lengths (B,)
    const int*   lab   = (const int*)d_in[2];    // seq_token_label (B,T)
    const float* wv    = (const float*)d_in[3];  // word_vec (V,E)
    const float* Wihf  = (const float*)d_in[4];
    const float* Whhf  = (const float*)d_in[5];
    const float* bf    = (const float*)d_in[6];
    const float* Wihb  = (const float*)d_in[7];
    const float* Whhb  = (const float*)d_in[8];
    const float* bb    = (const float*)d_in[9];
    const float* Wout  = (const float*)d_in[10];
    const float* bout  = (const float*)d_in[11];
    const float* st    = (const float*)d_in[12];
    const float* en    = (const float*)d_in[13];
    const float* tr    = (const float*)d_in[14];

    float* out       = (float*)d_out;
    float* preds_out = out + 1;                 // (B,T) as float
    float* feats     = out + 1 + BB * TT;       // (B,T,2H)

    const int nfeat = MTOT * 2 * HH;
    zero_kernel<<<(nfeat + 255) / 256, 256>>>(feats, nfeat);
    gemm_kernel<<<dim3(G4 / 128, MTOT / 128, 2), 256>>>(wi, lens, wv, Wihf, bf, Wihb, bb);
    lstm_kernel<<<dim3(BB / 2, 2), 512>>>(lens, feats, Whhf, Whhb);
    emis_kernel<<<MTOT / 8, 256>>>(feats, Wout, bout);
    crf_kernel<<<BB, 64>>>(lens, lab, st, en, tr, preds_out);
    finalize_kernel<<<1, 32>>>(out);
}

// round 7
// speedup vs baseline: 3.7867x; 3.7867x over previous
#include <cuda_runtime.h>
#include <math.h>

#define BB 64
#define TT 512
#define EE 256
#define HH 256
#define KK 9
#define G4 1024              // 4*H
#define MTOT (BB*TT)         // 32768

// ---------------- scratch (device globals; no allocations allowed) ----------
__device__ float g_gx_f[(size_t)MTOT * G4];   // forward input-gate preacts (+bias)
__device__ float g_gx_b[(size_t)MTOT * G4];   // backward input-gate preacts (+bias)
__device__ float g_WtF[(size_t)HH * G4];      // W_hh_f transposed: [k][n] = [256][1024]
__device__ float g_WtB[(size_t)HH * G4];      // W_hh_b transposed
__device__ int   g_perm[BB];                  // batches sorted by length (desc)
__device__ float g_emis[(size_t)MTOT * KK];   // emissions
__device__ float g_loss[BB];                  // per-batch (num - denom)

__device__ __forceinline__ float sigf(float x)  { return 1.0f / (1.0f + __expf(-x)); }
__device__ __forceinline__ float tanhff(float x){ return 1.0f - 2.0f / (__expf(2.0f * x) + 1.0f); }

// ---------------- zero feats region --------------------------------------
__global__ void zero_kernel(float* __restrict__ p, int n) {
    int i = blockIdx.x * blockDim.x + threadIdx.x;
    if (i < n) p[i] = 0.0f;
}

// ---------------- transpose W_hh (1024x256 -> 256x1024), both dirs --------
__global__ void prep_kernel(const float* __restrict__ Whh_f,
                            const float* __restrict__ Whh_b)
{
    __shared__ float tile[32][33];
    const float* __restrict__ W  = blockIdx.z ? Whh_b : Whh_f;
    float* __restrict__       Wt = blockIdx.z ? g_WtB : g_WtF;
    const int n0 = blockIdx.x * 32;   // 0..1023
    const int k0 = blockIdx.y * 32;   // 0..255
    const int tx = threadIdx.x & 31, ty = threadIdx.x >> 5;  // 32x8
#pragma unroll
    for (int i = 0; i < 32; i += 8)
        tile[ty + i][tx] = W[(size_t)(n0 + ty + i) * HH + k0 + tx];
    __syncthreads();
#pragma unroll
    for (int i = 0; i < 32; i += 8)
        Wt[(size_t)(k0 + ty + i) * G4 + n0 + tx] = tile[tx][ty + i];
}

// ---------------- sort batches by length (descending), odd-even ------------
__global__ void sort_kernel(const int* __restrict__ lens) {
    __shared__ int keys[BB];
    const int t = threadIdx.x;
    keys[t] = (lens[t] << 8) | t;     // unique keys -> deterministic order
    for (int phase = 0; phase < BB; phase++) {
        __syncthreads();
        if ((t & 1) == (phase & 1) && t + 1 < BB) {
            int a = keys[t], b = keys[t + 1];
            if (a < b) { keys[t] = b; keys[t + 1] = a; }   // descending
        }
    }
    __syncthreads();
    g_perm[t] = keys[t] & 255;
}

// ---------------- fused embedding-gather + input GEMM ---------------------
__global__ __launch_bounds__(256, 2)
void gemm_kernel(const int* __restrict__ word_inputs,
                 const int* __restrict__ lens,
                 const float* __restrict__ word_vec,
                 const float* __restrict__ Wf, const float* __restrict__ bf,
                 const float* __restrict__ Wb, const float* __restrict__ bb)
{
    const int dir = blockIdx.z;
    const float* __restrict__ Wih  = dir ? Wb : Wf;
    const float* __restrict__ bias = dir ? bb : bf;
    float* __restrict__ gx = dir ? g_gx_b : g_gx_f;

    const int m0 = blockIdx.y * 128;
    const int n0 = blockIdx.x * 128;
    const int bidx = m0 >> 9;
    const int t0   = m0 & 511;
    if (t0 >= lens[bidx]) return;    // gx rows t>=L never read downstream

    __shared__ float As[8][128];
    __shared__ float Bs[8][128];
    __shared__ int   sIdx[128];

    const int tid = threadIdx.x;
    if (tid < 128) sIdx[tid] = word_inputs[m0 + tid];
    __syncthreads();

    const int lr = tid >> 1;
    const int kq = (tid & 1) * 4;
    const int ty = tid >> 4, tx = tid & 15;

    const float* __restrict__ arow = word_vec + (size_t)sIdx[lr] * EE;
    const float* __restrict__ brow = Wih + (size_t)(n0 + lr) * EE;

    float acc[8][8];
#pragma unroll
    for (int i = 0; i < 8; i++)
#pragma unroll
        for (int j = 0; j < 8; j++) acc[i][j] = 0.0f;

    for (int k0 = 0; k0 < EE; k0 += 8) {
        float4 av = *(const float4*)(arow + k0 + kq);
        float4 bv = *(const float4*)(brow + k0 + kq);
        __syncthreads();
        As[kq + 0][lr] = av.x; As[kq + 1][lr] = av.y;
        As[kq + 2][lr] = av.z; As[kq + 3][lr] = av.w;
        Bs[kq + 0][lr] = bv.x; Bs[kq + 1][lr] = bv.y;
        Bs[kq + 2][lr] = bv.z; Bs[kq + 3][lr] = bv.w;
        __syncthreads();
#pragma unroll
        for (int kk = 0; kk < 8; kk++) {
            float4 a0 = *(const float4*)&As[kk][ty * 8];
            float4 a1 = *(const float4*)&As[kk][ty * 8 + 4];
            float4 b0 = *(const float4*)&Bs[kk][tx * 8];
            float4 b1 = *(const float4*)&Bs[kk][tx * 8 + 4];
            float a[8] = {a0.x, a0.y, a0.z, a0.w, a1.x, a1.y, a1.z, a1.w};
            float b[8] = {b0.x, b0.y, b0.z, b0.w, b1.x, b1.y, b1.z, b1.w};
#pragma unroll
            for (int i = 0; i < 8; i++)
#pragma unroll
                for (int j = 0; j < 8; j++)
                    acc[i][j] = fmaf(a[i], b[j], acc[i][j]);
        }
    }

    const float* bsrc = bias + n0 + tx * 8;
    float4 bb0 = *(const float4*)(bsrc);
    float4 bb1 = *(const float4*)(bsrc + 4);
    float bvals[8] = {bb0.x, bb0.y, bb0.z, bb0.w, bb1.x, bb1.y, bb1.z, bb1.w};
#pragma unroll
    for (int i = 0; i < 8; i++) {
        int m = m0 + ty * 8 + i;
        float* dst = gx + (size_t)m * G4 + n0 + tx * 8;
        float4 o0 = make_float4(acc[i][0] + bvals[0], acc[i][1] + bvals[1],
                                acc[i][2] + bvals[2], acc[i][3] + bvals[3]);
        float4 o1 = make_float4(acc[i][4] + bvals[4], acc[i][5] + bvals[5],
                                acc[i][6] + bvals[6], acc[i][7] + bvals[7]);
        *(float4*)(dst) = o0;
        *(float4*)(dst + 4) = o1;
    }
}

// ---------------- bidirectional LSTM recurrence (coalesced W^T) ------------
// grid (32, 2): blockIdx.x = sorted batch pair, blockIdx.y = direction.
// 512 threads. Thread t accumulates gate columns {2t, 2t+1} for both batches
// via coalesced float2 loads of Wt[k][n]. Gate preacts staged in SMEM; then
// threads [0,256) advance (c,h) for batch0 j=t, [256,512) for batch1 j=t-256.
__global__ __launch_bounds__(512, 1)
void lstm_kernel(const int* __restrict__ lens, float* __restrict__ feats)
{
    const int dir = blockIdx.y;
    const float* __restrict__ Wt = dir ? g_WtB : g_WtF;
    const float* __restrict__ gx = dir ? g_gx_b : g_gx_f;
    const int b0 = g_perm[2 * blockIdx.x];
    const int b1 = g_perm[2 * blockIdx.x + 1];
    const int L0 = lens[b0], L1 = lens[b1];
    const int Lmax = (L0 > L1) ? L0 : L1;

    __shared__ float h0s[HH], h1s[HH];
    __shared__ float pre0[G4], pre1[G4];

    const int t = threadIdx.x;
    if (t < HH) { h0s[t] = 0.0f; h1s[t] = 0.0f; }
    float c0 = 0.0f, c1 = 0.0f;

    const float2* __restrict__ W2 = (const float2*)Wt;  // [k][512 float2]
    __syncthreads();

    for (int s = 0; s < Lmax; s++) {
        const bool act0 = s < L0, act1 = s < L1;
        float a00 = 0, a01 = 0, a10 = 0, a11 = 0;
        const float4* __restrict__ h0v = (const float4*)h0s;
        const float4* __restrict__ h1v = (const float4*)h1s;
#pragma unroll 4
        for (int k4 = 0; k4 < HH / 4; k4++) {
            float4 ha = h0v[k4];
            float4 hb = h1v[k4];
            float2 w0 = W2[(size_t)(k4 * 4 + 0) * 512 + t];
            float2 w1 = W2[(size_t)(k4 * 4 + 1) * 512 + t];
            float2 w2 = W2[(size_t)(k4 * 4 + 2) * 512 + t];
            float2 w3 = W2[(size_t)(k4 * 4 + 3) * 512 + t];
            a00 = fmaf(w0.x, ha.x, a00); a01 = fmaf(w0.y, ha.x, a01);
            a10 = fmaf(w0.x, hb.x, a10); a11 = fmaf(w0.y, hb.x, a11);
            a00 = fmaf(w1.x, ha.y, a00); a01 = fmaf(w1.y, ha.y, a01);
            a10 = fmaf(w1.x, hb.y, a10); a11 = fmaf(w1.y, hb.y, a11);
            a00 = fmaf(w2.x, ha.z, a00); a01 = fmaf(w2.y, ha.z, a01);
            a10 = fmaf(w2.x, hb.z, a10); a11 = fmaf(w2.y, hb.z, a11);
            a00 = fmaf(w3.x, ha.w, a00); a01 = fmaf(w3.y, ha.w, a01);
            a10 = fmaf(w3.x, hb.w, a10); a11 = fmaf(w3.y, hb.w, a11);
        }
        const int t0 = dir ? (L0 - 1 - s) : s;
        const int t1 = dir ? (L1 - 1 - s) : s;
        if (act0) {
            float2 g = *(const float2*)(gx + (size_t)(b0 * TT + t0) * G4 + 2 * t);
            pre0[2 * t]     = a00 + g.x;
            pre0[2 * t + 1] = a01 + g.y;
        }
        if (act1) {
            float2 g = *(const float2*)(gx + (size_t)(b1 * TT + t1) * G4 + 2 * t);
            pre1[2 * t]     = a10 + g.x;
            pre1[2 * t + 1] = a11 + g.y;
        }
        __syncthreads();
        if (t < HH) {
            if (act0) {
                float iv = pre0[t], fv = pre0[t + 256], gv = pre0[t + 512], ov = pre0[t + 768];
                c0 = fmaf(sigf(fv), c0, sigf(iv) * tanhff(gv));
                float hv = sigf(ov) * tanhff(c0);
                h0s[t] = hv;
                feats[(size_t)(b0 * TT + t0) * (2 * HH) + dir * HH + t] = hv;
            }
        } else {
            const int j = t - HH;
            if (act1) {
                float iv = pre1[j], fv = pre1[j + 256], gv = pre1[j + 512], ov = pre1[j + 768];
                c1 = fmaf(sigf(fv), c1, sigf(iv) * tanhff(gv));
                float hv = sigf(ov) * tanhff(c1);
                h1s[j] = hv;
                feats[(size_t)(b1 * TT + t1) * (2 * HH) + dir * HH + j] = hv;
            }
        }
        __syncthreads();
    }
}

// ---------------- emissions: feats @ W_out^T + b_out ----------------------
__global__ void emis_kernel(const float* __restrict__ feats,
                            const float* __restrict__ Wout,
                            const float* __restrict__ bout)
{
    __shared__ float sW[KK][2 * HH];   // 18 KB
    const int tid = threadIdx.x;
    for (int i = tid; i < KK * 2 * HH; i += 256)
        sW[i / (2 * HH)][i % (2 * HH)] = Wout[i];
    __syncthreads();

    const int warp = tid >> 5, lane = tid & 31;
    const int row = blockIdx.x * 8 + warp;
    const float* __restrict__ fr = feats + (size_t)row * (2 * HH);
    float acc[KK];
#pragma unroll
    for (int k = 0; k < KK; k++) acc[k] = 0.0f;
#pragma unroll 4
    for (int it = 0; it < 16; it++) {
        float x = fr[it * 32 + lane];
#pragma unroll
        for (int k = 0; k < KK; k++) acc[k] = fmaf(x, sW[k][it * 32 + lane], acc[k]);
    }
#pragma unroll
    for (int k = 0; k < KK; k++) {
        float v = acc[k];
#pragma unroll
        for (int off = 16; off; off >>= 1) v += __shfl_xor_sync(0xffffffffu, v, off);
        if (lane == 0) g_emis[(size_t)row * KK + k] = v + bout[k];
    }
}

// ---------------- CRF: alpha + numerator (warp0), viterbi + preds (warp1) --
__global__ void crf_kernel(const int* __restrict__ lens, const int* __restrict__ labels,
                           const float* __restrict__ start_t, const float* __restrict__ end_t,
                           const float* __restrict__ trans, float* __restrict__ preds_out)
{
    const int b = blockIdx.x;
    const int L = lens[b];
    const int tid = threadIdx.x, warp = tid >> 5, lane = tid & 31;
    const float* __restrict__ em = g_emis + (size_t)b * TT * KK;
    __shared__ unsigned char hist[TT][KK];

    const float NEG = -1e30f;
    const int j = lane;
    float tr[KK];
#pragma unroll
    for (int i = 0; i < KK; i++) tr[i] = (j < KK) ? trans[i * KK + j] : 0.0f;

    if (warp == 0) {
        float score = (j < KK) ? (start_t[j] + em[j]) : NEG;
        for (int t = 1; t < L; t++) {
            float v[KK], mx = NEG;
#pragma unroll
            for (int i = 0; i < KK; i++) {
                v[i] = __shfl_sync(0xffffffffu, score, i) + tr[i];
                mx = fmaxf(mx, v[i]);
            }
            float sum = 0.0f;
#pragma unroll
            for (int i = 0; i < KK; i++) sum += __expf(v[i] - mx);
            float e = (j < KK) ? em[t * KK + j] : 0.0f;
            float nxt = mx + __logf(sum) + e;
            if (j < KK) score = nxt;
        }
        float z = (j < KK) ? (score + end_t[j]) : NEG;
        float mz = z;
#pragma unroll
        for (int off = 16; off; off >>= 1) mz = fmaxf(mz, __shfl_xor_sync(0xffffffffu, mz, off));
        float se = (j < KK) ? __expf(z - mz) : 0.0f;
#pragma unroll
        for (int off = 16; off; off >>= 1) se += __shfl_xor_sync(0xffffffffu, se, off);
        float denom = mz + __logf(se);

        const int* __restrict__ lab = labels + b * TT;
        float acc = 0.0f;
        for (int t = 1 + lane; t < L; t += 32) {
            int yp = lab[t - 1], y = lab[t];
            acc += trans[yp * KK + y] + em[t * KK + y];
        }
#pragma unroll
        for (int off = 16; off; off >>= 1) acc += __shfl_xor_sync(0xffffffffu, acc, off);
        if (lane == 0) {
            int y0 = lab[0], yl = lab[L - 1];
            float num = acc + start_t[y0] + em[y0] + end_t[yl];
            g_loss[b] = num - denom;
        }
    } else {
        float score = (j < KK) ? (start_t[j] + em[j]) : NEG;
        for (int t = 1; t < L; t++) {
            float best = NEG; int barg = 0;
#pragma unroll
            for (int i = 0; i < KK; i++) {
                float v = __shfl_sync(0xffffffffu, score, i) + tr[i];
                if (v > best) { best = v; barg = i; }
            }
            if (j < KK) {
                hist[t - 1][j] = (unsigned char)barg;
                score = best + em[t * KK + j];
            }
        }
        float z = (j < KK) ? (score + end_t[j]) : NEG;
        int idx = j;
#pragma unroll
        for (int off = 16; off; off >>= 1) {
            float oz = __shfl_xor_sync(0xffffffffu, z, off);
            int   oi = __shfl_xor_sync(0xffffffffu, idx, off);
            if (oz > z || (oz == z && oi < idx)) { z = oz; idx = oi; }
        }
        int best_last = __shfl_sync(0xffffffffu, idx, 0);

        float* __restrict__ po = preds_out + (size_t)b * TT;
        for (int t = L + lane; t < TT; t += 32) po[t] = 0.0f;
        if (lane == 0) {
            int cur = best_last;
            po[L - 1] = (float)cur;
            for (int t = L - 2; t >= 0; t--) { cur = hist[t][cur]; po[t] = (float)cur; }
        }
    }
}

// ---------------- deterministic loss reduction ----------------------------
__global__ void finalize_kernel(float* __restrict__ out) {
    if (threadIdx.x == 0) {
        float s = 0.0f;
        for (int i = 0; i < BB; i++) s += g_loss[i];
        out[0] = -s / (float)BB;
    }
}

// ---------------- launch ---------------------------------------------------
extern "C" void kernel_launch(void* const* d_in, const int* in_sizes, int n_in,
                              void* d_out, int out_size) {
    const int*   wi    = (const int*)d_in[0];
    const int*   lens  = (const int*)d_in[1];
    const int*   lab   = (const int*)d_in[2];
    const float* wv    = (const float*)d_in[3];
    const float* Wihf  = (const float*)d_in[4];
    const float* Whhf  = (const float*)d_in[5];
    const float* bf    = (const float*)d_in[6];
    const float* Wihb  = (const float*)d_in[7];
    const float* Whhb  = (const float*)d_in[8];
    const float* bb    = (const float*)d_in[9];
    const float* Wout  = (const float*)d_in[10];
    const float* bout  = (const float*)d_in[11];
    const float* st    = (const float*)d_in[12];
    const float* en    = (const float*)d_in[13];
    const float* tr    = (const float*)d_in[14];

    float* out       = (float*)d_out;
    float* preds_out = out + 1;
    float* feats     = out + 1 + BB * TT;

    const int nfeat = MTOT * 2 * HH;
    zero_kernel<<<(nfeat + 255) / 256, 256>>>(feats, nfeat);
    prep_kernel<<<dim3(G4 / 32, HH / 32, 2), 256>>>(Whhf, Whhb);
    sort_kernel<<<1, BB>>>(lens);
    gemm_kernel<<<dim3(G4 / 128, MTOT / 128, 2), 256>>>(wi, lens, wv, Wihf, bf, Wihb, bb);
    lstm_kernel<<<dim3(BB / 2, 2), 512>>>(lens, feats);
    emis_kernel<<<MTOT / 8, 256>>>(feats, Wout, bout);
    crf_kernel<<<BB, 64>>>(lens, lab, st, en, tr, preds_out);
    finalize_kernel<<<1, 32>>>(out);
}

// round 10
// speedup vs baseline: 4.3031x; 1.1364x over previous
#include <cuda_runtime.h>
#include <cstdint>
#include <math.h>

#define BB 64
#define TT 512
#define EE 256
#define HH 256
#define KK 9
#define G4 1024              // 4*H
#define MTOT (BB*TT)         // 32768

// ---------------- scratch (device globals; no allocations allowed) ----------
__device__ float g_gx_f[(size_t)MTOT * G4];   // forward input-gate preacts (+bias)
__device__ float g_gx_b[(size_t)MTOT * G4];   // backward input-gate preacts (+bias)
__device__ float g_WtF[(size_t)HH * G4];      // W_hh_f transposed: [k][n] = [256][1024]
__device__ float g_WtB[(size_t)HH * G4];      // W_hh_b transposed
__device__ int   g_perm[BB];                  // batches sorted by length (desc)
__device__ float g_emis[(size_t)MTOT * KK];   // emissions
__device__ float g_loss[BB];                  // per-batch (num - denom)

__device__ __forceinline__ float sigf(float x)  { return 1.0f / (1.0f + __expf(-x)); }
__device__ __forceinline__ float tanhff(float x){ return 1.0f - 2.0f / (__expf(2.0f * x) + 1.0f); }

__device__ __forceinline__ unsigned int smem_u32(const void* p) {
    unsigned int a;
    asm("{ .reg .u64 t; cvta.to.shared.u64 t, %1; cvt.u32.u64 %0, t; }" : "=r"(a) : "l"(p));
    return a;
}
__device__ __forceinline__ unsigned int mapa_rank(unsigned int a, unsigned int r) {
    unsigned int d;
    asm("mapa.shared::cluster.u32 %0, %1, %2;" : "=r"(d) : "r"(a), "r"(r));
    return d;
}
__device__ __forceinline__ void st_cluster(unsigned int a, float v) {
    asm volatile("st.shared::cluster.f32 [%0], %1;" :: "r"(a), "f"(v) : "memory");
}
__device__ __forceinline__ unsigned int ctarank() {
    unsigned int r; asm("mov.u32 %0, %%cluster_ctarank;" : "=r"(r)); return r;
}
#define CLUSTER_SYNC() do { \
    asm volatile("barrier.cluster.arrive.aligned;" ::: "memory"); \
    asm volatile("barrier.cluster.wait.aligned;"   ::: "memory"); \
} while (0)

// ---------------- zero feats region --------------------------------------
__global__ void zero_kernel(float* __restrict__ p, int n) {
    int i = blockIdx.x * blockDim.x + threadIdx.x;
    if (i < n) p[i] = 0.0f;
}

// ---------------- transpose W_hh (1024x256 -> 256x1024), both dirs --------
__global__ void prep_kernel(const float* __restrict__ Whh_f,
                            const float* __restrict__ Whh_b)
{
    __shared__ float tile[32][33];
    const float* __restrict__ W  = blockIdx.z ? Whh_b : Whh_f;
    float* __restrict__       Wt = blockIdx.z ? g_WtB : g_WtF;
    const int n0 = blockIdx.x * 32;
    const int k0 = blockIdx.y * 32;
    const int tx = threadIdx.x & 31, ty = threadIdx.x >> 5;
#pragma unroll
    for (int i = 0; i < 32; i += 8)
        tile[ty + i][tx] = W[(size_t)(n0 + ty + i) * HH + k0 + tx];
    __syncthreads();
#pragma unroll
    for (int i = 0; i < 32; i += 8)
        Wt[(size_t)(k0 + ty + i) * G4 + n0 + tx] = tile[tx][ty + i];
}

// ---------------- sort batches by length (descending), odd-even ------------
__global__ void sort_kernel(const int* __restrict__ lens) {
    __shared__ int keys[BB];
    const int t = threadIdx.x;
    keys[t] = (lens[t] << 8) | t;
    for (int phase = 0; phase < BB; phase++) {
        __syncthreads();
        if ((t & 1) == (phase & 1) && t + 1 < BB) {
            int a = keys[t], b = keys[t + 1];
            if (a < b) { keys[t] = b; keys[t + 1] = a; }
        }
    }
    __syncthreads();
    g_perm[t] = keys[t] & 255;
}

// ---------------- fused embedding-gather + input GEMM ---------------------
__global__ __launch_bounds__(256, 2)
void gemm_kernel(const int* __restrict__ word_inputs,
                 const int* __restrict__ lens,
                 const float* __restrict__ word_vec,
                 const float* __restrict__ Wf, const float* __restrict__ bf,
                 const float* __restrict__ Wb, const float* __restrict__ bb)
{
    const int dir = blockIdx.z;
    const float* __restrict__ Wih  = dir ? Wb : Wf;
    const float* __restrict__ bias = dir ? bb : bf;
    float* __restrict__ gx = dir ? g_gx_b : g_gx_f;

    const int m0 = blockIdx.y * 128;
    const int n0 = blockIdx.x * 128;
    const int bidx = m0 >> 9;
    const int t0   = m0 & 511;
    if (t0 >= lens[bidx]) return;

    __shared__ float As[8][128];
    __shared__ float Bs[8][128];
    __shared__ int   sIdx[128];

    const int tid = threadIdx.x;
    if (tid < 128) sIdx[tid] = word_inputs[m0 + tid];
    __syncthreads();

    const int lr = tid >> 1;
    const int kq = (tid & 1) * 4;
    const int ty = tid >> 4, tx = tid & 15;

    const float* __restrict__ arow = word_vec + (size_t)sIdx[lr] * EE;
    const float* __restrict__ brow = Wih + (size_t)(n0 + lr) * EE;

    float acc[8][8];
#pragma unroll
    for (int i = 0; i < 8; i++)
#pragma unroll
        for (int j = 0; j < 8; j++) acc[i][j] = 0.0f;

    for (int k0 = 0; k0 < EE; k0 += 8) {
        float4 av = *(const float4*)(arow + k0 + kq);
        float4 bv = *(const float4*)(brow + k0 + kq);
        __syncthreads();
        As[kq + 0][lr] = av.x; As[kq + 1][lr] = av.y;
        As[kq + 2][lr] = av.z; As[kq + 3][lr] = av.w;
        Bs[kq + 0][lr] = bv.x; Bs[kq + 1][lr] = bv.y;
        Bs[kq + 2][lr] = bv.z; Bs[kq + 3][lr] = bv.w;
        __syncthreads();
#pragma unroll
        for (int kk = 0; kk < 8; kk++) {
            float4 a0 = *(const float4*)&As[kk][ty * 8];
            float4 a1 = *(const float4*)&As[kk][ty * 8 + 4];
            float4 b0 = *(const float4*)&Bs[kk][tx * 8];
            float4 b1 = *(const float4*)&Bs[kk][tx * 8 + 4];
            float a[8] = {a0.x, a0.y, a0.z, a0.w, a1.x, a1.y, a1.z, a1.w};
            float b[8] = {b0.x, b0.y, b0.z, b0.w, b1.x, b1.y, b1.z, b1.w};
#pragma unroll
            for (int i = 0; i < 8; i++)
#pragma unroll
                for (int j = 0; j < 8; j++)
                    acc[i][j] = fmaf(a[i], b[j], acc[i][j]);
        }
    }

    const float* bsrc = bias + n0 + tx * 8;
    float4 bb0 = *(const float4*)(bsrc);
    float4 bb1 = *(const float4*)(bsrc + 4);
    float bvals[8] = {bb0.x, bb0.y, bb0.z, bb0.w, bb1.x, bb1.y, bb1.z, bb1.w};
#pragma unroll
    for (int i = 0; i < 8; i++) {
        int m = m0 + ty * 8 + i;
        float* dst = gx + (size_t)m * G4 + n0 + tx * 8;
        float4 o0 = make_float4(acc[i][0] + bvals[0], acc[i][1] + bvals[1],
                                acc[i][2] + bvals[2], acc[i][3] + bvals[3]);
        float4 o1 = make_float4(acc[i][4] + bvals[4], acc[i][5] + bvals[5],
                                acc[i][6] + bvals[6], acc[i][7] + bvals[7]);
        *(float4*)(dst) = o0;
        *(float4*)(dst + 4) = o1;
    }
}

// ---------------- bidirectional LSTM, 2-CTA cluster per (pair, dir) --------
// grid (32, 2, 2), cluster (1,1,2). rank = gate-column half:
//   rank 0 owns cols [0,512)    = i[0:256], f[0:256]
//   rank 1 owns cols [512,1024) = g[0:256], o[0:256]
// Thread t computes its column's dot(Wt_col, h) for both batches of the pair.
// rank0 DSMEM-pushes (i,f) preacts to rank1; rank1 holds c-state (thread t:
// batch=t>>8, j=t&255), computes h, pushes h back to rank0's SMEM.
__global__ __launch_bounds__(512, 1) __cluster_dims__(1, 1, 2)
void lstm_kernel(const int* __restrict__ lens, float* __restrict__ feats)
{
    const int dir = blockIdx.y;
    const float* __restrict__ Wt = dir ? g_WtB : g_WtF;
    const float* __restrict__ gx = dir ? g_gx_b : g_gx_f;
    const int b0 = g_perm[2 * blockIdx.x];
    const int b1 = g_perm[2 * blockIdx.x + 1];
    const int L0 = lens[b0], L1 = lens[b1];   // sorted: L0 >= L1
    const unsigned int rank = ctarank();

    __shared__ __align__(16) float hs[2][HH];      // h for both batches (replicated)
    __shared__ float preIF[2][512];                // rank1: receives i,f from rank0
    __shared__ float preGO[2][512];                // rank1: own g,o

    const int t = threadIdx.x;
    if (t < HH) { hs[0][t] = 0.0f; hs[1][t] = 0.0f; }

    // fixed remote addresses
    unsigned int rem_if0 = 0, rem_if1 = 0, rem_h = 0;
    if (rank == 0) {
        rem_if0 = mapa_rank(smem_u32(&preIF[0][t]), 1);
        rem_if1 = mapa_rank(smem_u32(&preIF[1][t]), 1);
    } else {
        rem_h = mapa_rank(smem_u32(&hs[t >> 8][t & 255]), 0);
    }

    const float* __restrict__ wp = Wt + rank * 512 + t;
    float creg = 0.0f;
    CLUSTER_SYNC();

    for (int s = 0; s < L0; s++) {
        const bool act1 = s < L1;
        float acc0 = 0.0f, acc1 = 0.0f;
        const float4* __restrict__ h0v = (const float4*)hs[0];
        const float4* __restrict__ h1v = (const float4*)hs[1];
#pragma unroll 8
        for (int k4 = 0; k4 < HH / 4; k4++) {
            float4 ha = h0v[k4], hb = h1v[k4];
            float w0 = wp[(size_t)(4 * k4 + 0) * G4];
            float w1 = wp[(size_t)(4 * k4 + 1) * G4];
            float w2 = wp[(size_t)(4 * k4 + 2) * G4];
            float w3 = wp[(size_t)(4 * k4 + 3) * G4];
            acc0 = fmaf(w0, ha.x, acc0); acc1 = fmaf(w0, hb.x, acc1);
            acc0 = fmaf(w1, ha.y, acc0); acc1 = fmaf(w1, hb.y, acc1);
            acc0 = fmaf(w2, ha.z, acc0); acc1 = fmaf(w2, hb.z, acc1);
            acc0 = fmaf(w3, ha.w, acc0); acc1 = fmaf(w3, hb.w, acc1);
        }
        const int t0 = dir ? (L0 - 1 - s) : s;
        const int t1 = dir ? (L1 - 1 - s) : s;
        acc0 += gx[(size_t)(b0 * TT + t0) * G4 + rank * 512 + t];
        if (act1) acc1 += gx[(size_t)(b1 * TT + t1) * G4 + rank * 512 + t];

        if (rank == 0) {
            st_cluster(rem_if0, acc0);
            if (act1) st_cluster(rem_if1, acc1);
        } else {
            preGO[0][t] = acc0;
            if (act1) preGO[1][t] = acc1;
        }
        CLUSTER_SYNC();   // preacts visible in rank1; all h reads done

        if (rank == 1) {
            const int b = t >> 8, j = t & 255;
            if (b == 0 || act1) {
                float iv = preIF[b][j], fv = preIF[b][j + 256];
                float gv = preGO[b][j], ov = preGO[b][j + 256];
                creg = fmaf(sigf(fv), creg, sigf(iv) * tanhff(gv));
                float hv = sigf(ov) * tanhff(creg);
                hs[b][j] = hv;          // local copy
                st_cluster(rem_h, hv);  // rank0's copy
                const int bb = b ? b1 : b0;
                const int tt = b ? t1 : t0;
                feats[(size_t)(bb * TT + tt) * (2 * HH) + dir * HH + j] = hv;
            }
        }
        CLUSTER_SYNC();   // new h visible in both CTAs
    }
}

// ---------------- emissions: feats @ W_out^T + b_out ----------------------
__global__ void emis_kernel(const float* __restrict__ feats,
                            const float* __restrict__ Wout,
                            const float* __restrict__ bout)
{
    __shared__ float sW[KK][2 * HH];
    const int tid = threadIdx.x;
    for (int i = tid; i < KK * 2 * HH; i += 256)
        sW[i / (2 * HH)][i % (2 * HH)] = Wout[i];
    __syncthreads();

    const int warp = tid >> 5, lane = tid & 31;
    const int row = blockIdx.x * 8 + warp;
    const float* __restrict__ fr = feats + (size_t)row * (2 * HH);
    float acc[KK];
#pragma unroll
    for (int k = 0; k < KK; k++) acc[k] = 0.0f;
#pragma unroll 4
    for (int it = 0; it < 16; it++) {
        float x = fr[it * 32 + lane];
#pragma unroll
        for (int k = 0; k < KK; k++) acc[k] = fmaf(x, sW[k][it * 32 + lane], acc[k]);
    }
#pragma unroll
    for (int k = 0; k < KK; k++) {
        float v = acc[k];
#pragma unroll
        for (int off = 16; off; off >>= 1) v += __shfl_xor_sync(0xffffffffu, v, off);
        if (lane == 0) g_emis[(size_t)row * KK + k] = v + bout[k];
    }
}

// ---------------- CRF: alpha + numerator (warp0), viterbi + preds (warp1) --
__global__ void crf_kernel(const int* __restrict__ lens, const int* __restrict__ labels,
                           const float* __restrict__ start_t, const float* __restrict__ end_t,
                           const float* __restrict__ trans, float* __restrict__ preds_out)
{
    const int b = blockIdx.x;
    const int L = lens[b];
    const int tid = threadIdx.x, warp = tid >> 5, lane = tid & 31;
    const float* __restrict__ em = g_emis + (size_t)b * TT * KK;
    __shared__ unsigned char hist[TT][KK];

    const float NEG = -1e30f;
    const int j = lane;
    float tr[KK];
#pragma unroll
    for (int i = 0; i < KK; i++) tr[i] = (j < KK) ? trans[i * KK + j] : 0.0f;

    if (warp == 0) {
        float score = (j < KK) ? (start_t[j] + em[j]) : NEG;
        for (int t = 1; t < L; t++) {
            float v[KK], mx = NEG;
#pragma unroll
            for (int i = 0; i < KK; i++) {
                v[i] = __shfl_sync(0xffffffffu, score, i) + tr[i];
                mx = fmaxf(mx, v[i]);
            }
            float sum = 0.0f;
#pragma unroll
            for (int i = 0; i < KK; i++) sum += __expf(v[i] - mx);
            float e = (j < KK) ? em[t * KK + j] : 0.0f;
            float nxt = mx + __logf(sum) + e;
            if (j < KK) score = nxt;
        }
        float z = (j < KK) ? (score + end_t[j]) : NEG;
        float mz = z;
#pragma unroll
        for (int off = 16; off; off >>= 1) mz = fmaxf(mz, __shfl_xor_sync(0xffffffffu, mz, off));
        float se = (j < KK) ? __expf(z - mz) : 0.0f;
#pragma unroll
        for (int off = 16; off; off >>= 1) se += __shfl_xor_sync(0xffffffffu, se, off);
        float denom = mz + __logf(se);

        const int* __restrict__ lab = labels + b * TT;
        float acc = 0.0f;
        for (int t = 1 + lane; t < L; t += 32) {
            int yp = lab[t - 1], y = lab[t];
            acc += trans[yp * KK + y] + em[t * KK + y];
        }
#pragma unroll
        for (int off = 16; off; off >>= 1) acc += __shfl_xor_sync(0xffffffffu, acc, off);
        if (lane == 0) {
            int y0 = lab[0], yl = lab[L - 1];
            float num = acc + start_t[y0] + em[y0] + end_t[yl];
            g_loss[b] = num - denom;
        }
    } else {
        float score = (j < KK) ? (start_t[j] + em[j]) : NEG;
        for (int t = 1; t < L; t++) {
            float best = NEG; int barg = 0;
#pragma unroll
            for (int i = 0; i < KK; i++) {
                float v = __shfl_sync(0xffffffffu, score, i) + tr[i];
                if (v > best) { best = v; barg = i; }
            }
            if (j < KK) {
                hist[t - 1][j] = (unsigned char)barg;
                score = best + em[t * KK + j];
            }
        }
        float z = (j < KK) ? (score + end_t[j]) : NEG;
        int idx = j;
#pragma unroll
        for (int off = 16; off; off >>= 1) {
            float oz = __shfl_xor_sync(0xffffffffu, z, off);
            int   oi = __shfl_xor_sync(0xffffffffu, idx, off);
            if (oz > z || (oz == z && oi < idx)) { z = oz; idx = oi; }
        }
        int best_last = __shfl_sync(0xffffffffu, idx, 0);

        float* __restrict__ po = preds_out + (size_t)b * TT;
        for (int t = L + lane; t < TT; t += 32) po[t] = 0.0f;
        if (lane == 0) {
            int cur = best_last;
            po[L - 1] = (float)cur;
            for (int t = L - 2; t >= 0; t--) { cur = hist[t][cur]; po[t] = (float)cur; }
        }
    }
}

// ---------------- deterministic loss reduction ----------------------------
__global__ void finalize_kernel(float* __restrict__ out) {
    if (threadIdx.x == 0) {
        float s = 0.0f;
        for (int i = 0; i < BB; i++) s += g_loss[i];
        out[0] = -s / (float)BB;
    }
}

// ---------------- launch ---------------------------------------------------
extern "C" void kernel_launch(void* const* d_in, const int* in_sizes, int n_in,
                              void* d_out, int out_size) {
    const int*   wi    = (const int*)d_in[0];
    const int*   lens  = (const int*)d_in[1];
    const int*   lab   = (const int*)d_in[2];
    const float* wv    = (const float*)d_in[3];
    const float* Wihf  = (const float*)d_in[4];
    const float* Whhf  = (const float*)d_in[5];
    const float* bf    = (const float*)d_in[6];
    const float* Wihb  = (const float*)d_in[7];
    const float* Whhb  = (const float*)d_in[8];
    const float* bb    = (const float*)d_in[9];
    const float* Wout  = (const float*)d_in[10];
    const float* bout  = (const float*)d_in[11];
    const float* st    = (const float*)d_in[12];
    const float* en    = (const float*)d_in[13];
    const float* tr    = (const float*)d_in[14];

    float* out       = (float*)d_out;
    float* preds_out = out + 1;
    float* feats     = out + 1 + BB * TT;

    const int nfeat = MTOT * 2 * HH;
    zero_kernel<<<(nfeat + 255) / 256, 256>>>(feats, nfeat);
    prep_kernel<<<dim3(G4 / 32, HH / 32, 2), 256>>>(Whhf, Whhb);
    sort_kernel<<<1, BB>>>(lens);
    gemm_kernel<<<dim3(G4 / 128, MTOT / 128, 2), 256>>>(wi, lens, wv, Wihf, bf, Wihb, bb);
    lstm_kernel<<<dim3(BB / 2, 2, 2), 512>>>(lens, feats);
    emis_kernel<<<MTOT / 8, 256>>>(feats, Wout, bout);
    crf_kernel<<<BB, 64>>>(lens, lab, st, en, tr, preds_out);
    finalize_kernel<<<1, 32>>>(out);
}